// round 16
// baseline (speedup 1.0000x reference)
#include <cuda_runtime.h>
#include <math.h>
#include <math_constants.h>
#include <cstdint>

#define BATCH 128
#define T     250
#define DIN   700
#define H     256
#define DOUT  20
#define MTOT  (BATCH*T)

// ---------------- scratch (static device globals; no dynamic alloc) ----------
__device__ float g_XW1[MTOT*H];
__device__ float g_W11t[(H+1)*H];      // zero row at index H
__device__ float g_W12t[(H+1)*H];
__device__ float g_W22t[(H+1)*H];
__device__ float g_Wot [(H+1)*DOUT];
__device__ __align__(16) float g_Whi[H*DIN];
__device__ __align__(16) float g_Wlo[H*DIN];

// ---------------- tf32 helpers ------------------------------------------------
__device__ __forceinline__ void split_tf32(float x, float& hi, float& lo) {
    uint32_t h; asm("cvt.rna.tf32.f32 %0, %1;" : "=r"(h) : "f"(x));
    hi = __uint_as_float(h);
    float r = x - hi;
    uint32_t l; asm("cvt.rna.tf32.f32 %0, %1;" : "=r"(l) : "f"(r));
    lo = __uint_as_float(l);
}
__device__ __forceinline__ void mma_tf32(float* d, const uint32_t* a, uint32_t b0, uint32_t b1) {
    asm volatile(
        "mma.sync.aligned.m16n8k8.row.col.f32.tf32.tf32.f32 "
        "{%0,%1,%2,%3}, {%4,%5,%6,%7}, {%8,%9}, {%0,%1,%2,%3};"
        : "+f"(d[0]), "+f"(d[1]), "+f"(d[2]), "+f"(d[3])
        : "r"(a[0]), "r"(a[1]), "r"(a[2]), "r"(a[3]), "r"(b0), "r"(b1));
}

// ---------------- block-8 gather: 8 independent LDGs, no tail -----------------
__device__ __forceinline__ void gather8(const int* __restrict__ lst, int blk,
                                        const float* __restrict__ W, int stride, int col,
                                        float& h0, float& h1, float& h2, float& h3)
{
    const int4* lp = (const int4*)(lst + (blk << 3));
    int4 a = lp[0], b = lp[1];
    float w0 = W[a.x*stride + col];
    float w1 = W[a.y*stride + col];
    float w2 = W[a.z*stride + col];
    float w3 = W[a.w*stride + col];
    float w4 = W[b.x*stride + col];
    float w5 = W[b.y*stride + col];
    float w6 = W[b.z*stride + col];
    float w7 = W[b.w*stride + col];
    h0 += w0; h1 += w1; h2 += w2; h3 += w3;
    h0 += w4; h1 += w5; h2 += w6; h3 += w7;
}

// ---------------- transpose weights (+ zero rows) ------------------------------
__global__ void transpose_all(const float* __restrict__ W11, const float* __restrict__ W12,
                              const float* __restrict__ W22, const float* __restrict__ Wo)
{
    int idx = blockIdx.x * blockDim.x + threadIdx.x;
    if (idx < H*H) {
        int r = idx / H, c = idx % H;
        g_W11t[c*H + r] = W11[idx];
        g_W12t[c*H + r] = W12[idx];
        g_W22t[c*H + r] = W22[idx];
    }
    if (idx < DOUT*H) {
        int r = idx / H, c = idx % H;
        g_Wot[c*DOUT + r] = Wo[idx];
    }
    if (idx < H) {
        g_W11t[H*H + idx] = 0.f;
        g_W12t[H*H + idx] = 0.f;
        g_W22t[H*H + idx] = 0.f;
    }
    if (idx < DOUT) g_Wot[H*DOUT + idx] = 0.f;
}

// ---------------- pre-split Wi1 into tf32 hi/lo -------------------------------
__global__ void presplit_Wi1(const float* __restrict__ Wi1)
{
    int idx = blockIdx.x * blockDim.x + threadIdx.x;
    if (idx < H*DIN) {
        float hi, lo;
        split_tf32(Wi1[idx], hi, lo);
        g_Whi[idx] = hi;
        g_Wlo[idx] = lo;
    }
}

// smem: 4 tiles of 128 rows x 16 k-floats, row stride 20 floats (80 B)  [R13]
#define RS    20
#define TSZF  (128*RS)
#define SM_TOTB (4*TSZF*4)        // 40960 bytes

// ---------------- Phase A: 3xTF32 mma.sync GEMM (R13 proven version) ----------
__global__ __launch_bounds__(256, 2)
void tf32_gemm_input(const float* __restrict__ A,
                     const float* __restrict__ bias1, const float* __restrict__ bias2)
{
    extern __shared__ float smf[];
    float* As_hi = smf;
    float* As_lo = smf + TSZF;
    float* Bs_hi = smf + 2*TSZF;
    float* Bs_lo = smf + 3*TSZF;

    int tid = threadIdx.x;
    int wid = tid >> 5, lane = tid & 31;
    int gid = lane >> 2, tig = lane & 3;
    int bm = blockIdx.x * 128, bn = blockIdx.y * 128;
    int wm = (wid >> 2) * 64;
    int wn = (wid & 3) * 32;

    float acc[4][4][4] = {};
    const int NCH = (DIN + 15) / 16;  // 44

    float4 pva[2], pwh[2], pwl[2];
    #pragma unroll
    for (int i = 0; i < 2; ++i) {
        int f = tid + i*256, row = f >> 2, q = f & 3;
        int gk = q * 4;
        pva[i] = *(const float4*)(A     + (size_t)(bm + row)*DIN + gk);
        pwh[i] = *(const float4*)(g_Whi + (size_t)(bn + row)*DIN + gk);
        pwl[i] = *(const float4*)(g_Wlo + (size_t)(bn + row)*DIN + gk);
    }

    for (int ch = 0; ch < NCH; ++ch) {
        #pragma unroll
        for (int i = 0; i < 2; ++i) {
            int f = tid + i*256, row = f >> 2, q = f & 3;
            float4 ah, al;
            split_tf32(pva[i].x, ah.x, al.x); split_tf32(pva[i].y, ah.y, al.y);
            split_tf32(pva[i].z, ah.z, al.z); split_tf32(pva[i].w, ah.w, al.w);
            int off = row*RS + q*4;
            *(float4*)(As_hi + off) = ah;
            *(float4*)(As_lo + off) = al;
            *(float4*)(Bs_hi + off) = pwh[i];
            *(float4*)(Bs_lo + off) = pwl[i];
        }
        __syncthreads();

        if (ch + 1 < NCH) {
            int k0 = (ch + 1) * 16;
            #pragma unroll
            for (int i = 0; i < 2; ++i) {
                int f = tid + i*256, row = f >> 2, q = f & 3;
                int gk = k0 + q * 4;
                if (gk < DIN) {
                    pva[i] = *(const float4*)(A     + (size_t)(bm + row)*DIN + gk);
                    pwh[i] = *(const float4*)(g_Whi + (size_t)(bn + row)*DIN + gk);
                    pwl[i] = *(const float4*)(g_Wlo + (size_t)(bn + row)*DIN + gk);
                } else {
                    pva[i] = make_float4(0.f,0.f,0.f,0.f);
                    pwh[i] = make_float4(0.f,0.f,0.f,0.f);
                    pwl[i] = make_float4(0.f,0.f,0.f,0.f);
                }
            }
        }

        #pragma unroll
        for (int s = 0; s < 2; ++s) {
            int koff = s * 8 + tig;
            uint32_t ah[4][4], al[4][4];
            #pragma unroll
            for (int mt = 0; mt < 4; ++mt) {
                int r0 = wm + mt*16 + gid;
                const float* ph = As_hi + r0*RS + koff;
                const float* pl = As_lo + r0*RS + koff;
                ah[mt][0] = __float_as_uint(ph[0]);
                ah[mt][1] = __float_as_uint(ph[8*RS]);
                ah[mt][2] = __float_as_uint(ph[4]);
                ah[mt][3] = __float_as_uint(ph[8*RS+4]);
                al[mt][0] = __float_as_uint(pl[0]);
                al[mt][1] = __float_as_uint(pl[8*RS]);
                al[mt][2] = __float_as_uint(pl[4]);
                al[mt][3] = __float_as_uint(pl[8*RS+4]);
            }
            #pragma unroll
            for (int nt = 0; nt < 4; ++nt) {
                int nr = wn + nt*8 + gid;
                const float* qh = Bs_hi + nr*RS + koff;
                const float* ql = Bs_lo + nr*RS + koff;
                uint32_t bh0 = __float_as_uint(qh[0]);
                uint32_t bh1 = __float_as_uint(qh[4]);
                uint32_t bl0 = __float_as_uint(ql[0]);
                uint32_t bl1 = __float_as_uint(ql[4]);
                #pragma unroll
                for (int mt = 0; mt < 4; ++mt) {
                    mma_tf32(acc[mt][nt], ah[mt], bh0, bh1);
                    mma_tf32(acc[mt][nt], ah[mt], bl0, bl1);
                    mma_tf32(acc[mt][nt], al[mt], bh0, bh1);
                }
            }
        }
        __syncthreads();
    }

    #pragma unroll
    for (int nt = 0; nt < 4; ++nt) {
        int col = bn + wn + nt*8 + 2*tig;
        float b0 = bias1[col]   + bias2[col];
        float b1 = bias1[col+1] + bias2[col+1];
        #pragma unroll
        for (int mt = 0; mt < 4; ++mt) {
            int r0 = bm + wm + mt*16 + gid;
            float2 o0 = make_float2(acc[mt][nt][0] + b0, acc[mt][nt][1] + b1);
            float2 o1 = make_float2(acc[mt][nt][2] + b0, acc[mt][nt][3] + b1);
            __stcs((float2*)&g_XW1[(size_t)r0*H + col],     o0);
            __stcs((float2*)&g_XW1[(size_t)(r0+8)*H + col], o1);
        }
    }
}

// ---------------- megafused recurrent pipeline, 544 threads -------------------
// Same as R13 except barrier A is now PER-GROUP (bar.sync 1/2, 256 threads):
// no cross-group data crosses barrier A, so groups no longer wait on each
// other's gather skew twice per iteration. Barrier B (full CTA) publishes lists.
__global__ __launch_bounds__(544)
void mega_recurrent(const float* __restrict__ mem1_0, const float* __restrict__ tau_adp1,
                    const float* __restrict__ tau_m1,
                    const float* __restrict__ mem2_0, const float* __restrict__ tau_adp2,
                    const float* __restrict__ tau_m2,
                    const float* __restrict__ b12, const float* __restrict__ b22,
                    const float* __restrict__ memo0, const float* __restrict__ tau_m_o,
                    const float* __restrict__ bo, float* __restrict__ outp)
{
    int b   = blockIdx.x;
    int tid = threadIdx.x;
    int j   = tid & 255;
    int wid = tid >> 5, lane = tid & 31;
    int grp = (tid < 256) ? 0 : (tid < 512 ? 1 : 2);

    __shared__ __align__(16) int list1[2][H+8];
    __shared__ __align__(16) int list2[2][H+8];
    __shared__ int scnt1[2], scnt2[2];
    __shared__ __align__(16) int wnp1[8];
    __shared__ __align__(16) int wnp2[8];

    float alpha = 0.f, ro = 0.f, mem = 0.f, bb = 0.01f, sp = 0.f, drv = 0.f, bs2 = 0.f;
    const float* dr = g_XW1 + (size_t)b*T*H + j;
    float alpha_o = 0.f, memo = 0.f, acc = 0.f, bol = 0.f;
    bool act = false;

    if (grp == 0) {
        alpha = (float)exp(-1.0 / (double)tau_m1[j]);
        ro    = (float)exp(-1.0 / (double)tau_adp1[j]);
        mem   = mem1_0[b*H + j];
        drv   = __ldcs(dr);
    } else if (grp == 1) {
        alpha = (float)exp(-1.0 / (double)tau_m2[j]);
        ro    = (float)exp(-1.0 / (double)tau_adp2[j]);
        mem   = mem2_0[b*H + j];
        bs2   = b12[j] + b22[j];
    } else {
        act = lane < DOUT;
        int l = act ? lane : 0;
        alpha_o = (float)exp(-1.0 / (double)tau_m_o[l]);
        memo    = memo0[b*DOUT + l];
        bol     = bo[l];
    }

    if (tid == 0) { scnt1[0] = 0; scnt1[1] = 0; scnt2[0] = 0; scnt2[1] = 0; }
    if (tid < 8)  { list1[0][tid] = H; list1[1][tid] = H; }
    else if (tid < 16) { list2[0][tid-8] = H; list2[1][tid-8] = H; }
    __syncthreads();

    for (int t = 0; t <= T + 1; ++t) {
        int p = t & 1;
        unsigned bal = 0u;

        if (grp == 0) {
            if (t < T) {
                float drv_next = (t+1 < T) ? __ldcs(dr + (size_t)(t+1)*H) : 0.f;
                int nb = (scnt1[p] + 7) >> 3;
                float h0 = drv, h1 = 0.f, h2 = 0.f, h3 = 0.f;
                for (int blk = 0; blk < nb; ++blk)
                    gather8(list1[p], blk, g_W11t, H, j, h0, h1, h2, h3);
                float h = (h0 + h1) + (h2 + h3);

                bb = ro*bb + (1.f - ro)*sp;
                float Bt = 0.01f + 1.8f*bb;
                mem = mem*alpha + (1.f - alpha)*h - Bt*sp;
                sp  = (mem - Bt > 0.f) ? 1.f : 0.f;

                bal = __ballot_sync(0xFFFFFFFFu, sp != 0.f);
                if (lane == 0) wnp1[wid] = __popc(bal);
                drv = drv_next;
            }
        } else if (grp == 1) {
            if (t >= 1 && t <= T) {
                int nb1 = (scnt1[p] + 7) >> 3;
                int nb2 = (scnt2[p] + 7) >> 3;
                int nbm = nb1 > nb2 ? nb1 : nb2;
                float h0 = bs2, h1 = 0.f, h2 = 0.f, h3 = 0.f;
                for (int blk = 0; blk < nbm; ++blk) {
                    bool v1 = blk < nb1, v2 = blk < nb2;
                    float wa[8], wb[8];
                    if (v1) {
                        const int4* lp = (const int4*)(&list1[p][blk << 3]);
                        int4 a = lp[0], bq = lp[1];
                        wa[0]=g_W12t[a.x*H+j];  wa[1]=g_W12t[a.y*H+j];
                        wa[2]=g_W12t[a.z*H+j];  wa[3]=g_W12t[a.w*H+j];
                        wa[4]=g_W12t[bq.x*H+j]; wa[5]=g_W12t[bq.y*H+j];
                        wa[6]=g_W12t[bq.z*H+j]; wa[7]=g_W12t[bq.w*H+j];
                    }
                    if (v2) {
                        const int4* lp = (const int4*)(&list2[p][blk << 3]);
                        int4 a = lp[0], bq = lp[1];
                        wb[0]=g_W22t[a.x*H+j];  wb[1]=g_W22t[a.y*H+j];
                        wb[2]=g_W22t[a.z*H+j];  wb[3]=g_W22t[a.w*H+j];
                        wb[4]=g_W22t[bq.x*H+j]; wb[5]=g_W22t[bq.y*H+j];
                        wb[6]=g_W22t[bq.z*H+j]; wb[7]=g_W22t[bq.w*H+j];
                    }
                    if (v1) {
                        h0 += wa[0]; h1 += wa[1]; h2 += wa[2]; h3 += wa[3];
                        h0 += wa[4]; h1 += wa[5]; h2 += wa[6]; h3 += wa[7];
                    }
                    if (v2) {
                        h0 += wb[0]; h1 += wb[1]; h2 += wb[2]; h3 += wb[3];
                        h0 += wb[4]; h1 += wb[5]; h2 += wb[6]; h3 += wb[7];
                    }
                }
                float h = (h0 + h1) + (h2 + h3);

                bb = ro*bb + (1.f - ro)*sp;
                float Bt = 0.01f + 1.8f*bb;
                mem = mem*alpha + (1.f - alpha)*h - Bt*sp;
                sp  = (mem - Bt > 0.f) ? 1.f : 0.f;

                bal = __ballot_sync(0xFFFFFFFFu, sp != 0.f);
                if (lane == 0) wnp2[wid - 8] = __popc(bal);
            }
        } else {
            if (t >= 2) {
                int u = t - 2;
                int nb = (scnt2[p] + 7) >> 3;
                int l = act ? lane : 0;
                float o0 = bol, o1 = 0.f, o2 = 0.f, o3 = 0.f;
                for (int blk = 0; blk < nb; ++blk)
                    gather8(list2[p], blk, g_Wot, DOUT, l, o0, o1, o2, o3);
                memo = memo*alpha_o + (1.f - alpha_o)*((o0 + o1) + (o2 + o3));
                float v = act ? memo : -CUDART_INF_F;
                #pragma unroll
                for (int off = 16; off; off >>= 1)
                    v = fmaxf(v, __shfl_xor_sync(0xFFFFFFFFu, v, off));
                float e = act ? expf(memo - v) : 0.f;
                float s = e;
                #pragma unroll
                for (int off = 16; off; off >>= 1)
                    s += __shfl_xor_sync(0xFFFFFFFFu, s, off);
                if (u > 10) acc += e / s;
            }
        }

        // ---- barrier A: per-group only (no cross-group data crosses A) ----
        if (grp == 0)      asm volatile("bar.sync 1, 256;" ::: "memory");
        else if (grp == 1) asm volatile("bar.sync 2, 256;" ::: "memory");

        int np = p ^ 1;
        if (grp == 0 && t < T) {
            int4 w0 = *(const int4*)&wnp1[0];
            int4 w1 = *(const int4*)&wnp1[4];
            int cnt8[8] = {w0.x,w0.y,w0.z,w0.w,w1.x,w1.y,w1.z,w1.w};
            int base = 0, total = 0;
            #pragma unroll
            for (int w = 0; w < 8; ++w) {
                total += cnt8[w];
                if (w < wid) base += cnt8[w];
            }
            if (sp != 0.f) {
                int pos = base + __popc(bal & ((1u << lane) - 1u));
                list1[np][pos] = j;
            }
            if (j < 8) list1[np][total + j] = H;
            if (tid == 0) scnt1[np] = total;
        } else if (grp == 1 && t >= 1 && t <= T) {
            int w8 = wid - 8;
            int4 w0 = *(const int4*)&wnp2[0];
            int4 w1 = *(const int4*)&wnp2[4];
            int cnt8[8] = {w0.x,w0.y,w0.z,w0.w,w1.x,w1.y,w1.z,w1.w};
            int base = 0, total = 0;
            #pragma unroll
            for (int w = 0; w < 8; ++w) {
                total += cnt8[w];
                if (w < w8) base += cnt8[w];
            }
            if (sp != 0.f) {
                int pos = base + __popc(bal & ((1u << lane) - 1u));
                list2[np][pos] = j;
            }
            if (j < 8) list2[np][total + j] = H;
            if (tid == 256) scnt2[np] = total;
        }
        __syncthreads();    // barrier B: publish lists for next iteration
    }

    if (grp == 2 && act) outp[b*DOUT + lane] = acc;
}

// ---------------- launch ------------------------------------------------------
extern "C" void kernel_launch(void* const* d_in, const int* in_sizes, int n_in,
                              void* d_out, int out_size)
{
    const float* x        = (const float*)d_in[0];
    const float* mem1_0   = (const float*)d_in[1];
    const float* mem2_0   = (const float*)d_in[2];
    const float* memo_0   = (const float*)d_in[3];
    const float* Wi1      = (const float*)d_in[4];
    const float* bi1      = (const float*)d_in[5];
    const float* W11      = (const float*)d_in[6];
    const float* b11      = (const float*)d_in[7];
    const float* W12      = (const float*)d_in[8];
    const float* b12      = (const float*)d_in[9];
    const float* W22      = (const float*)d_in[10];
    const float* b22      = (const float*)d_in[11];
    const float* Wo       = (const float*)d_in[12];
    const float* bo       = (const float*)d_in[13];
    const float* tau_adp1 = (const float*)d_in[14];
    const float* tau_adp2 = (const float*)d_in[15];
    const float* tau_m1   = (const float*)d_in[16];
    const float* tau_m2   = (const float*)d_in[17];
    const float* tau_mo   = (const float*)d_in[18];
    float* outp = (float*)d_out;

    cudaFuncSetAttribute(tf32_gemm_input, cudaFuncAttributeMaxDynamicSharedMemorySize, SM_TOTB);

    // 1) transpose weights (+ zero rows)
    transpose_all<<<(H*H + 255)/256, 256>>>(W11, W12, W22, Wo);

    // 2) pre-split Wi1 into tf32 hi/lo
    presplit_Wi1<<<(H*DIN + 255)/256, 256>>>(Wi1);

    // 3) XW1 = x @ Wi1.T + bi1 + b11   (R13 proven GEMM)
    dim3 gA(MTOT/128, H/128);
    tf32_gemm_input<<<gA, 256, SM_TOTB>>>(x, bi1, b11);

    // 4) megafused pipelined recurrences + output   <-- profiled slot
    mega_recurrent<<<BATCH, 544>>>(mem1_0, tau_adp1, tau_m1,
                                   mem2_0, tau_adp2, tau_m2,
                                   b12, b22, memo_0, tau_mo, bo, outp);
}

// round 17
// speedup vs baseline: 1.5271x; 1.5271x over previous
#include <cuda_runtime.h>
#include <math.h>
#include <math_constants.h>
#include <cstdint>

#define BATCH 128
#define T     250
#define DIN   700
#define H     256
#define DOUT  20
#define MTOT  (BATCH*T)

// ---------------- scratch (static device globals; no dynamic alloc) ----------
__device__ float g_XW1[MTOT*H];
__device__ float g_W11t[(H+1)*H];      // zero row at index H
__device__ float g_W12t[(H+1)*H];
__device__ float g_W22t[(H+1)*H];
__device__ float g_Wot [(H+1)*DOUT];
__device__ __align__(16) float g_Whi[H*DIN];
__device__ __align__(16) float g_Wlo[H*DIN];

// ---------------- tf32 helpers ------------------------------------------------
__device__ __forceinline__ void split_tf32(float x, float& hi, float& lo) {
    uint32_t h; asm("cvt.rna.tf32.f32 %0, %1;" : "=r"(h) : "f"(x));
    hi = __uint_as_float(h);
    float r = x - hi;
    uint32_t l; asm("cvt.rna.tf32.f32 %0, %1;" : "=r"(l) : "f"(r));
    lo = __uint_as_float(l);
}
__device__ __forceinline__ void mma_tf32(float* d, const uint32_t* a, uint32_t b0, uint32_t b1) {
    asm volatile(
        "mma.sync.aligned.m16n8k8.row.col.f32.tf32.tf32.f32 "
        "{%0,%1,%2,%3}, {%4,%5,%6,%7}, {%8,%9}, {%0,%1,%2,%3};"
        : "+f"(d[0]), "+f"(d[1]), "+f"(d[2]), "+f"(d[3])
        : "r"(a[0]), "r"(a[1]), "r"(a[2]), "r"(a[3]), "r"(b0), "r"(b1));
}

// ---------------- block-8 gather: 8 independent LDGs, no tail -----------------
__device__ __forceinline__ void gather8(const int* __restrict__ lst, int blk,
                                        const float* __restrict__ W, int stride, int col,
                                        float& h0, float& h1, float& h2, float& h3)
{
    const int4* lp = (const int4*)(lst + (blk << 3));
    int4 a = lp[0], b = lp[1];
    float w0 = W[a.x*stride + col];
    float w1 = W[a.y*stride + col];
    float w2 = W[a.z*stride + col];
    float w3 = W[a.w*stride + col];
    float w4 = W[b.x*stride + col];
    float w5 = W[b.y*stride + col];
    float w6 = W[b.z*stride + col];
    float w7 = W[b.w*stride + col];
    h0 += w0; h1 += w1; h2 += w2; h3 += w3;
    h0 += w4; h1 += w5; h2 += w6; h3 += w7;
}

// ---------------- transpose weights (+ zero rows) ------------------------------
__global__ void transpose_all(const float* __restrict__ W11, const float* __restrict__ W12,
                              const float* __restrict__ W22, const float* __restrict__ Wo)
{
    int idx = blockIdx.x * blockDim.x + threadIdx.x;
    if (idx < H*H) {
        int r = idx / H, c = idx % H;
        g_W11t[c*H + r] = W11[idx];
        g_W12t[c*H + r] = W12[idx];
        g_W22t[c*H + r] = W22[idx];
    }
    if (idx < DOUT*H) {
        int r = idx / H, c = idx % H;
        g_Wot[c*DOUT + r] = Wo[idx];
    }
    if (idx < H) {
        g_W11t[H*H + idx] = 0.f;
        g_W12t[H*H + idx] = 0.f;
        g_W22t[H*H + idx] = 0.f;
    }
    if (idx < DOUT) g_Wot[H*DOUT + idx] = 0.f;
}

// ---------------- pre-split Wi1 into tf32 hi/lo -------------------------------
__global__ void presplit_Wi1(const float* __restrict__ Wi1)
{
    int idx = blockIdx.x * blockDim.x + threadIdx.x;
    if (idx < H*DIN) {
        float hi, lo;
        split_tf32(Wi1[idx], hi, lo);
        g_Whi[idx] = hi;
        g_Wlo[idx] = lo;
    }
}

// smem: 4 tiles of 128 rows x 16 k-floats, row stride 20 floats (80 B)  [R13]
#define RS    20
#define TSZF  (128*RS)
#define SM_TOTB (4*TSZF*4)        // 40960 bytes

// ---------------- Phase A: 3xTF32 mma.sync GEMM (R13 + term-major MMA order) --
__global__ __launch_bounds__(256, 2)
void tf32_gemm_input(const float* __restrict__ A,
                     const float* __restrict__ bias1, const float* __restrict__ bias2)
{
    extern __shared__ float smf[];
    float* As_hi = smf;
    float* As_lo = smf + TSZF;
    float* Bs_hi = smf + 2*TSZF;
    float* Bs_lo = smf + 3*TSZF;

    int tid = threadIdx.x;
    int wid = tid >> 5, lane = tid & 31;
    int gid = lane >> 2, tig = lane & 3;
    int bm = blockIdx.x * 128, bn = blockIdx.y * 128;
    int wm = (wid >> 2) * 64;
    int wn = (wid & 3) * 32;

    float acc[4][4][4] = {};
    const int NCH = (DIN + 15) / 16;  // 44

    float4 pva[2], pwh[2], pwl[2];
    #pragma unroll
    for (int i = 0; i < 2; ++i) {
        int f = tid + i*256, row = f >> 2, q = f & 3;
        int gk = q * 4;
        pva[i] = *(const float4*)(A     + (size_t)(bm + row)*DIN + gk);
        pwh[i] = *(const float4*)(g_Whi + (size_t)(bn + row)*DIN + gk);
        pwl[i] = *(const float4*)(g_Wlo + (size_t)(bn + row)*DIN + gk);
    }

    for (int ch = 0; ch < NCH; ++ch) {
        #pragma unroll
        for (int i = 0; i < 2; ++i) {
            int f = tid + i*256, row = f >> 2, q = f & 3;
            float4 ah, al;
            split_tf32(pva[i].x, ah.x, al.x); split_tf32(pva[i].y, ah.y, al.y);
            split_tf32(pva[i].z, ah.z, al.z); split_tf32(pva[i].w, ah.w, al.w);
            int off = row*RS + q*4;
            *(float4*)(As_hi + off) = ah;
            *(float4*)(As_lo + off) = al;
            *(float4*)(Bs_hi + off) = pwh[i];
            *(float4*)(Bs_lo + off) = pwl[i];
        }
        __syncthreads();

        if (ch + 1 < NCH) {
            int k0 = (ch + 1) * 16;
            #pragma unroll
            for (int i = 0; i < 2; ++i) {
                int f = tid + i*256, row = f >> 2, q = f & 3;
                int gk = k0 + q * 4;
                if (gk < DIN) {
                    pva[i] = *(const float4*)(A     + (size_t)(bm + row)*DIN + gk);
                    pwh[i] = *(const float4*)(g_Whi + (size_t)(bn + row)*DIN + gk);
                    pwl[i] = *(const float4*)(g_Wlo + (size_t)(bn + row)*DIN + gk);
                } else {
                    pva[i] = make_float4(0.f,0.f,0.f,0.f);
                    pwh[i] = make_float4(0.f,0.f,0.f,0.f);
                    pwl[i] = make_float4(0.f,0.f,0.f,0.f);
                }
            }
        }

        #pragma unroll
        for (int s = 0; s < 2; ++s) {
            int koff = s * 8 + tig;
            uint32_t ah[4][4], al[4][4];
            #pragma unroll
            for (int mt = 0; mt < 4; ++mt) {
                int r0 = wm + mt*16 + gid;
                const float* ph = As_hi + r0*RS + koff;
                const float* pl = As_lo + r0*RS + koff;
                ah[mt][0] = __float_as_uint(ph[0]);
                ah[mt][1] = __float_as_uint(ph[8*RS]);
                ah[mt][2] = __float_as_uint(ph[4]);
                ah[mt][3] = __float_as_uint(ph[8*RS+4]);
                al[mt][0] = __float_as_uint(pl[0]);
                al[mt][1] = __float_as_uint(pl[8*RS]);
                al[mt][2] = __float_as_uint(pl[4]);
                al[mt][3] = __float_as_uint(pl[8*RS+4]);
            }
            #pragma unroll
            for (int nt = 0; nt < 4; ++nt) {
                int nr = wn + nt*8 + gid;
                const float* qh = Bs_hi + nr*RS + koff;
                const float* ql = Bs_lo + nr*RS + koff;
                uint32_t bh0 = __float_as_uint(qh[0]);
                uint32_t bh1 = __float_as_uint(qh[4]);
                uint32_t bl0 = __float_as_uint(ql[0]);
                uint32_t bl1 = __float_as_uint(ql[4]);
                // term-major: consecutive MMAs hit different accumulators
                // (per-acc term order unchanged: bh, bl, lh -> bit-identical)
                #pragma unroll
                for (int mt = 0; mt < 4; ++mt)
                    mma_tf32(acc[mt][nt], ah[mt], bh0, bh1);
                #pragma unroll
                for (int mt = 0; mt < 4; ++mt)
                    mma_tf32(acc[mt][nt], ah[mt], bl0, bl1);
                #pragma unroll
                for (int mt = 0; mt < 4; ++mt)
                    mma_tf32(acc[mt][nt], al[mt], bh0, bh1);
            }
        }
        __syncthreads();
    }

    #pragma unroll
    for (int nt = 0; nt < 4; ++nt) {
        int col = bn + wn + nt*8 + 2*tig;
        float b0 = bias1[col]   + bias2[col];
        float b1 = bias1[col+1] + bias2[col+1];
        #pragma unroll
        for (int mt = 0; mt < 4; ++mt) {
            int r0 = bm + wm + mt*16 + gid;
            float2 o0 = make_float2(acc[mt][nt][0] + b0, acc[mt][nt][1] + b1);
            float2 o1 = make_float2(acc[mt][nt][2] + b0, acc[mt][nt][3] + b1);
            __stcs((float2*)&g_XW1[(size_t)r0*H + col],     o0);
            __stcs((float2*)&g_XW1[(size_t)(r0+8)*H + col], o1);
        }
    }
}

// ---------------- megafused recurrent pipeline, 544 threads (R13 verbatim) ----
__global__ __launch_bounds__(544)
void mega_recurrent(const float* __restrict__ mem1_0, const float* __restrict__ tau_adp1,
                    const float* __restrict__ tau_m1,
                    const float* __restrict__ mem2_0, const float* __restrict__ tau_adp2,
                    const float* __restrict__ tau_m2,
                    const float* __restrict__ b12, const float* __restrict__ b22,
                    const float* __restrict__ memo0, const float* __restrict__ tau_m_o,
                    const float* __restrict__ bo, float* __restrict__ outp)
{
    int b   = blockIdx.x;
    int tid = threadIdx.x;
    int j   = tid & 255;
    int wid = tid >> 5, lane = tid & 31;
    int grp = (tid < 256) ? 0 : (tid < 512 ? 1 : 2);

    __shared__ __align__(16) int list1[2][H+8];
    __shared__ __align__(16) int list2[2][H+8];
    __shared__ int scnt1[2], scnt2[2];
    __shared__ __align__(16) int wnp1[8];
    __shared__ __align__(16) int wnp2[8];

    float alpha = 0.f, ro = 0.f, mem = 0.f, bb = 0.01f, sp = 0.f, drv = 0.f, bs2 = 0.f;
    const float* dr = g_XW1 + (size_t)b*T*H + j;
    float alpha_o = 0.f, memo = 0.f, acc = 0.f, bol = 0.f;
    bool act = false;

    if (grp == 0) {
        alpha = (float)exp(-1.0 / (double)tau_m1[j]);
        ro    = (float)exp(-1.0 / (double)tau_adp1[j]);
        mem   = mem1_0[b*H + j];
        drv   = __ldcs(dr);
    } else if (grp == 1) {
        alpha = (float)exp(-1.0 / (double)tau_m2[j]);
        ro    = (float)exp(-1.0 / (double)tau_adp2[j]);
        mem   = mem2_0[b*H + j];
        bs2   = b12[j] + b22[j];
    } else {
        act = lane < DOUT;
        int l = act ? lane : 0;
        alpha_o = (float)exp(-1.0 / (double)tau_m_o[l]);
        memo    = memo0[b*DOUT + l];
        bol     = bo[l];
    }

    if (tid == 0) { scnt1[0] = 0; scnt1[1] = 0; scnt2[0] = 0; scnt2[1] = 0; }
    if (tid < 8)  { list1[0][tid] = H; list1[1][tid] = H; }
    else if (tid < 16) { list2[0][tid-8] = H; list2[1][tid-8] = H; }
    __syncthreads();

    for (int t = 0; t <= T + 1; ++t) {
        int p = t & 1;
        unsigned bal = 0u;

        if (grp == 0) {
            if (t < T) {
                float drv_next = (t+1 < T) ? __ldcs(dr + (size_t)(t+1)*H) : 0.f;
                int nb = (scnt1[p] + 7) >> 3;
                float h0 = drv, h1 = 0.f, h2 = 0.f, h3 = 0.f;
                for (int blk = 0; blk < nb; ++blk)
                    gather8(list1[p], blk, g_W11t, H, j, h0, h1, h2, h3);
                float h = (h0 + h1) + (h2 + h3);

                bb = ro*bb + (1.f - ro)*sp;
                float Bt = 0.01f + 1.8f*bb;
                mem = mem*alpha + (1.f - alpha)*h - Bt*sp;
                sp  = (mem - Bt > 0.f) ? 1.f : 0.f;

                bal = __ballot_sync(0xFFFFFFFFu, sp != 0.f);
                if (lane == 0) wnp1[wid] = __popc(bal);
                drv = drv_next;
            }
        } else if (grp == 1) {
            if (t >= 1 && t <= T) {
                int nb1 = (scnt1[p] + 7) >> 3;
                int nb2 = (scnt2[p] + 7) >> 3;
                int nbm = nb1 > nb2 ? nb1 : nb2;
                float h0 = bs2, h1 = 0.f, h2 = 0.f, h3 = 0.f;
                for (int blk = 0; blk < nbm; ++blk) {
                    bool v1 = blk < nb1, v2 = blk < nb2;
                    float wa[8], wb[8];
                    if (v1) {
                        const int4* lp = (const int4*)(&list1[p][blk << 3]);
                        int4 a = lp[0], bq = lp[1];
                        wa[0]=g_W12t[a.x*H+j];  wa[1]=g_W12t[a.y*H+j];
                        wa[2]=g_W12t[a.z*H+j];  wa[3]=g_W12t[a.w*H+j];
                        wa[4]=g_W12t[bq.x*H+j]; wa[5]=g_W12t[bq.y*H+j];
                        wa[6]=g_W12t[bq.z*H+j]; wa[7]=g_W12t[bq.w*H+j];
                    }
                    if (v2) {
                        const int4* lp = (const int4*)(&list2[p][blk << 3]);
                        int4 a = lp[0], bq = lp[1];
                        wb[0]=g_W22t[a.x*H+j];  wb[1]=g_W22t[a.y*H+j];
                        wb[2]=g_W22t[a.z*H+j];  wb[3]=g_W22t[a.w*H+j];
                        wb[4]=g_W22t[bq.x*H+j]; wb[5]=g_W22t[bq.y*H+j];
                        wb[6]=g_W22t[bq.z*H+j]; wb[7]=g_W22t[bq.w*H+j];
                    }
                    if (v1) {
                        h0 += wa[0]; h1 += wa[1]; h2 += wa[2]; h3 += wa[3];
                        h0 += wa[4]; h1 += wa[5]; h2 += wa[6]; h3 += wa[7];
                    }
                    if (v2) {
                        h0 += wb[0]; h1 += wb[1]; h2 += wb[2]; h3 += wb[3];
                        h0 += wb[4]; h1 += wb[5]; h2 += wb[6]; h3 += wb[7];
                    }
                }
                float h = (h0 + h1) + (h2 + h3);

                bb = ro*bb + (1.f - ro)*sp;
                float Bt = 0.01f + 1.8f*bb;
                mem = mem*alpha + (1.f - alpha)*h - Bt*sp;
                sp  = (mem - Bt > 0.f) ? 1.f : 0.f;

                bal = __ballot_sync(0xFFFFFFFFu, sp != 0.f);
                if (lane == 0) wnp2[wid - 8] = __popc(bal);
            }
        } else {
            if (t >= 2) {
                int u = t - 2;
                int nb = (scnt2[p] + 7) >> 3;
                int l = act ? lane : 0;
                float o0 = bol, o1 = 0.f, o2 = 0.f, o3 = 0.f;
                for (int blk = 0; blk < nb; ++blk)
                    gather8(list2[p], blk, g_Wot, DOUT, l, o0, o1, o2, o3);
                memo = memo*alpha_o + (1.f - alpha_o)*((o0 + o1) + (o2 + o3));
                float v = act ? memo : -CUDART_INF_F;
                #pragma unroll
                for (int off = 16; off; off >>= 1)
                    v = fmaxf(v, __shfl_xor_sync(0xFFFFFFFFu, v, off));
                float e = act ? expf(memo - v) : 0.f;
                float s = e;
                #pragma unroll
                for (int off = 16; off; off >>= 1)
                    s += __shfl_xor_sync(0xFFFFFFFFu, s, off);
                if (u > 10) acc += e / s;
            }
        }
        __syncthreads();    // ballots/wnp visible; all list[p] reads complete

        int np = p ^ 1;
        if (grp == 0 && t < T) {
            int4 w0 = *(const int4*)&wnp1[0];
            int4 w1 = *(const int4*)&wnp1[4];
            int cnt8[8] = {w0.x,w0.y,w0.z,w0.w,w1.x,w1.y,w1.z,w1.w};
            int base = 0, total = 0;
            #pragma unroll
            for (int w = 0; w < 8; ++w) {
                total += cnt8[w];
                if (w < wid) base += cnt8[w];
            }
            if (sp != 0.f) {
                int pos = base + __popc(bal & ((1u << lane) - 1u));
                list1[np][pos] = j;
            }
            if (j < 8) list1[np][total + j] = H;
            if (tid == 0) scnt1[np] = total;
        } else if (grp == 1 && t >= 1 && t <= T) {
            int w8 = wid - 8;
            int4 w0 = *(const int4*)&wnp2[0];
            int4 w1 = *(const int4*)&wnp2[4];
            int cnt8[8] = {w0.x,w0.y,w0.z,w0.w,w1.x,w1.y,w1.z,w1.w};
            int base = 0, total = 0;
            #pragma unroll
            for (int w = 0; w < 8; ++w) {
                total += cnt8[w];
                if (w < w8) base += cnt8[w];
            }
            if (sp != 0.f) {
                int pos = base + __popc(bal & ((1u << lane) - 1u));
                list2[np][pos] = j;
            }
            if (j < 8) list2[np][total + j] = H;
            if (tid == 256) scnt2[np] = total;
        }
        __syncthreads();    // list[np] ready for next iter
    }

    if (grp == 2 && act) outp[b*DOUT + lane] = acc;
}

// ---------------- launch ------------------------------------------------------
extern "C" void kernel_launch(void* const* d_in, const int* in_sizes, int n_in,
                              void* d_out, int out_size)
{
    const float* x        = (const float*)d_in[0];
    const float* mem1_0   = (const float*)d_in[1];
    const float* mem2_0   = (const float*)d_in[2];
    const float* memo_0   = (const float*)d_in[3];
    const float* Wi1      = (const float*)d_in[4];
    const float* bi1      = (const float*)d_in[5];
    const float* W11      = (const float*)d_in[6];
    const float* b11      = (const float*)d_in[7];
    const float* W12      = (const float*)d_in[8];
    const float* b12      = (const float*)d_in[9];
    const float* W22      = (const float*)d_in[10];
    const float* b22      = (const float*)d_in[11];
    const float* Wo       = (const float*)d_in[12];
    const float* bo       = (const float*)d_in[13];
    const float* tau_adp1 = (const float*)d_in[14];
    const float* tau_adp2 = (const float*)d_in[15];
    const float* tau_m1   = (const float*)d_in[16];
    const float* tau_m2   = (const float*)d_in[17];
    const float* tau_mo   = (const float*)d_in[18];
    float* outp = (float*)d_out;

    cudaFuncSetAttribute(tf32_gemm_input, cudaFuncAttributeMaxDynamicSharedMemorySize, SM_TOTB);

    // 1) transpose weights (+ zero rows)
    transpose_all<<<(H*H + 255)/256, 256>>>(W11, W12, W22, Wo);

    // 2) pre-split Wi1 into tf32 hi/lo
    presplit_Wi1<<<(H*DIN + 255)/256, 256>>>(Wi1);

    // 3) XW1 = x @ Wi1.T + bi1 + b11   (term-major MMA ordering)
    dim3 gA(MTOT/128, H/128);
    tf32_gemm_input<<<gA, 256, SM_TOTB>>>(x, bi1, b11);

    // 4) megafused pipelined recurrences + output (R13 verbatim)  <-- profiled
    mega_recurrent<<<BATCH, 544>>>(mem1_0, tau_adp1, tau_m1,
                                   mem2_0, tau_adp2, tau_m2,
                                   b12, b22, memo_0, tau_mo, bo, outp);
}